// round 14
// baseline (speedup 1.0000x reference)
#include <cuda_runtime.h>
#include <cuda_bf16.h>
#include <math.h>

// ---------------- constants ----------------
#define LAYERS 12
#define HEADS  12
#define EMB    768
#define DHEAD  64
#define VOCAB  50257
#define BATCH  4
#define SEQ    1024
#define TOK    (BATCH * SEQ)          // 4096
#define E3     (3 * EMB)              // 2304
#define E4     (4 * EMB)              // 3072
#define KW     (EMB / 2)              // 384 words (k-pairs) for K=768
#define KW4    (E4 / 2)               // 1536 words for K=3072

// GEMM smem geometry (words): stride 20/row -> conflict-free ldmatrix
#define GSTR   20
#define GMAT   (128 * GSTR * 4)       // 10240 B per matrix buffer
#define GSTAGE (4 * GMAT)             // 40960 B per stage (Ah,Al,Bh,Bl)
#define GSMEM  (2 * GSTAGE)           // 81920 B total (2 stages)

// ---------------- scratch (__device__ globals: no cudaMalloc allowed) ------
__device__ float g_h  [(size_t)TOK * EMB];
__device__ float g_a  [(size_t)TOK * EMB];
__device__ float g_y  [(size_t)TOK * EMB];
__device__ float g_qkv[(size_t)TOK * E3];
__device__ float g_att[(size_t)BATCH * HEADS * SEQ * SEQ];
__device__ float g_fc [(size_t)TOK * E4];

// pre-split weights, TRANSPOSED: [N][K2] packed bf16x2 hi/lo words
__device__ unsigned g_wqkv_h[(size_t)LAYERS * E3 * KW];
__device__ unsigned g_wqkv_l[(size_t)LAYERS * E3 * KW];
__device__ unsigned g_wap_h [(size_t)LAYERS * EMB * KW];
__device__ unsigned g_wap_l [(size_t)LAYERS * EMB * KW];
__device__ unsigned g_wfc_h [(size_t)LAYERS * E4 * KW];
__device__ unsigned g_wfc_l [(size_t)LAYERS * E4 * KW];
__device__ unsigned g_wfp_h [(size_t)LAYERS * EMB * KW4];
__device__ unsigned g_wfp_l [(size_t)LAYERS * EMB * KW4];
__device__ unsigned g_wlm_h [(size_t)VOCAB * KW];
__device__ unsigned g_wlm_l [(size_t)VOCAB * KW];
// pre-split activations (reused per GEMM; sized for largest A = TOK x E4)
__device__ unsigned g_ah[(size_t)TOK * KW4];
__device__ unsigned g_al[(size_t)TOK * KW4];

// ---------------- helpers ----------------
__device__ __forceinline__ float gelu_f(float x) {
    float x3 = x * x * x;
    return 0.5f * x * (1.0f + tanhf(0.7978845608028654f * (x + 0.044715f * x3)));
}

// split two consecutive-k floats into packed bf16x2 hi and lo words
__device__ __forceinline__ void split2(float f0, float f1,
                                       unsigned& hi, unsigned& lo) {
    __nv_bfloat16 h0 = __float2bfloat16(f0);
    __nv_bfloat16 h1 = __float2bfloat16(f1);
    __nv_bfloat16 l0 = __float2bfloat16(f0 - __bfloat162float(h0));
    __nv_bfloat16 l1 = __float2bfloat16(f1 - __bfloat162float(h1));
    hi = ((unsigned)__bfloat16_as_ushort(h1) << 16) | __bfloat16_as_ushort(h0);
    lo = ((unsigned)__bfloat16_as_ushort(l1) << 16) | __bfloat16_as_ushort(l0);
}

// D += A*B  (m16n8k16 bf16, row.col, fp32 accum)
__device__ __forceinline__ void mma_bf16(float* c, const unsigned* a, const unsigned* b) {
    asm volatile(
        "mma.sync.aligned.m16n8k16.row.col.f32.bf16.bf16.f32 "
        "{%0,%1,%2,%3}, {%4,%5,%6,%7}, {%8,%9}, {%0,%1,%2,%3};\n"
        : "+f"(c[0]), "+f"(c[1]), "+f"(c[2]), "+f"(c[3])
        : "r"(a[0]), "r"(a[1]), "r"(a[2]), "r"(a[3]),
          "r"(b[0]), "r"(b[1]));
}

__device__ __forceinline__ void ldsm4(unsigned* r, unsigned addr) {
    asm volatile("ldmatrix.sync.aligned.m8n8.x4.shared.b16 {%0,%1,%2,%3}, [%4];"
        : "=r"(r[0]), "=r"(r[1]), "=r"(r[2]), "=r"(r[3]) : "r"(addr));
}

__device__ __forceinline__ unsigned cvta_s(const void* p) {
    return (unsigned)__cvta_generic_to_shared(p);
}

// cp.async 16B with zero-fill when srcsize == 0
__device__ __forceinline__ void cp16(unsigned dst, const void* src, unsigned ss) {
    asm volatile("cp.async.cg.shared.global [%0], [%1], 16, %2;"
                 :: "r"(dst), "l"(src), "r"(ss) : "memory");
}
__device__ __forceinline__ void cp_commit() {
    asm volatile("cp.async.commit_group;" ::: "memory");
}
__device__ __forceinline__ void cp_wait1() {
    asm volatile("cp.async.wait_group 1;" ::: "memory");
}

__device__ __forceinline__ float warp_sum(float v) {
    #pragma unroll
    for (int o = 16; o > 0; o >>= 1) v += __shfl_xor_sync(0xffffffffu, v, o);
    return v;
}
__device__ __forceinline__ float warp_max(float v) {
    #pragma unroll
    for (int o = 16; o > 0; o >>= 1) v = fmaxf(v, __shfl_xor_sync(0xffffffffu, v, o));
    return v;
}
__device__ __forceinline__ float block_sum(float v, float* sm) {
    v = warp_sum(v);
    int w = threadIdx.x >> 5, l = threadIdx.x & 31;
    if (l == 0) sm[w] = v;
    __syncthreads();
    float r = (l < 8) ? sm[l] : 0.0f;
    r = warp_sum(r);
    __syncthreads();
    return r;
}
__device__ __forceinline__ float block_max(float v, float* sm) {
    v = warp_max(v);
    int w = threadIdx.x >> 5, l = threadIdx.x & 31;
    if (l == 0) sm[w] = v;
    __syncthreads();
    float r = (l < 8) ? sm[l] : -3.0e38f;
    r = warp_max(r);
    __syncthreads();
    return r;
}

// ---------------- weight split + transpose (once per launch) --------------
__global__ __launch_bounds__(256) void wsplitT_kernel(
    const float* __restrict__ W, unsigned* __restrict__ hi,
    unsigned* __restrict__ lo, int K2, int N,
    size_t wstride, size_t ostride)
{
    __shared__ float s0[32][33], s1[32][33];
    const float* Wl = W + (size_t)blockIdx.z * wstride;
    int kp0 = blockIdx.x * 32;
    int n0  = blockIdx.y * 32;
    int tx = threadIdx.x & 31, ty = threadIdx.x >> 5;
    #pragma unroll
    for (int i = ty; i < 32; i += 8) {
        int kp = kp0 + i;
        int n = n0 + tx;
        float v0 = 0.0f, v1 = 0.0f;
        if (n < N) {
            v0 = Wl[(size_t)(2 * kp) * N + n];
            v1 = Wl[(size_t)(2 * kp + 1) * N + n];
        }
        s0[i][tx] = v0; s1[i][tx] = v1;
    }
    __syncthreads();
    unsigned* hil = hi + (size_t)blockIdx.z * ostride;
    unsigned* lol = lo + (size_t)blockIdx.z * ostride;
    #pragma unroll
    for (int i = ty; i < 32; i += 8) {
        int n = n0 + i;
        if (n < N) {
            unsigned h, l;
            split2(s0[tx][i], s1[tx][i], h, l);
            hil[(size_t)n * K2 + kp0 + tx] = h;
            lol[(size_t)n * K2 + kp0 + tx] = l;
        }
    }
}

// activations: A[M,K] fp32 (pairs contiguous along K) -> hi/lo words
__global__ __launch_bounds__(256) void asplit_kernel(
    const float* __restrict__ A, unsigned* __restrict__ hi,
    unsigned* __restrict__ lo, int total_words)
{
    int idx = blockIdx.x * 256 + threadIdx.x;
    if (idx < total_words) {
        float2 v = ((const float2*)A)[idx];
        unsigned h, l;
        split2(v.x, v.y, h, l);
        hi[idx] = h; lo[idx] = l;
    }
}

// ---------------- embedding ----------------
__global__ __launch_bounds__(256) void embed_kernel(
    const int* __restrict__ x, const float* __restrict__ wte,
    const float* __restrict__ wpe, float* __restrict__ h)
{
    int i = blockIdx.x * 256 + threadIdx.x;
    if (i < TOK * EMB) {
        int t = i / EMB;
        int e = i - t * EMB;
        int s = t & (SEQ - 1);
        h[i] = wte[(size_t)x[t] * EMB + e] + wpe[(size_t)s * EMB + e];
    }
}

// ---------------- layernorm (row = 768) ----------------
__global__ __launch_bounds__(256) void ln_kernel(
    const float* __restrict__ x, const float* __restrict__ g,
    const float* __restrict__ b, float* __restrict__ y)
{
    __shared__ float red[8];
    int row = blockIdx.x;
    const float* xr = x + (size_t)row * EMB;
    int tid = threadIdx.x;
    float v0 = xr[tid], v1 = xr[tid + 256], v2 = xr[tid + 512];
    float s  = v0 + v1 + v2;
    float s2 = v0 * v0 + v1 * v1 + v2 * v2;
    s  = block_sum(s,  red);
    __syncthreads();
    s2 = block_sum(s2, red);
    float mean = s * (1.0f / EMB);
    float var  = s2 * (1.0f / EMB) - mean * mean;
    float inv  = rsqrtf(var + 1e-5f);
    float* yr = y + (size_t)row * EMB;
    yr[tid]       = (v0 - mean) * inv * g[tid]       + b[tid];
    yr[tid + 256] = (v1 - mean) * inv * g[tid + 256] + b[tid + 256];
    yr[tid + 512] = (v2 - mean) * inv * g[tid + 512] + b[tid + 512];
}

// ---------------- split-bf16 tensor-core GEMM (cp.async 2-stage) ----------
// C[M,N] = A[M,K] @ B^T (both [rows][K2] packed bf16x2 hi/lo words).
// EPI: 0=write 1=gelu 2=residual-accum.
// Block tile 128x128, k-tile 16 words (32 k), cp.async double buffer.
// 8 warps 4(m) x 2(n); warp tile 32x64 = 2 x 8 m16n8k16 fragments.
// Row stride 20 words: every ldmatrix 8-row phase hits 32 distinct banks.
template <int EPI>
__global__ __launch_bounds__(256) void mma_gemm_kernel(
    const unsigned* __restrict__ A_h, const unsigned* __restrict__ A_l,
    const unsigned* __restrict__ B_h, const unsigned* __restrict__ B_l,
    const float* __restrict__ bias, float* __restrict__ C,
    int M, int N, int K2)
{
    extern __shared__ unsigned gsm[];
    unsigned sb = cvta_s(gsm);

    int tid  = threadIdx.x;
    int lane = tid & 31;
    int wid  = tid >> 5;
    int g    = lane >> 2;      // 0..7
    int t4   = lane & 3;       // 0..3
    int wm   = (wid & 3) * 32;
    int wn   = (wid >> 2) * 64;

    int bm = blockIdx.y * 128;
    int bn = blockIdx.x * 128;

    float acc[2][8][4];
    #pragma unroll
    for (int mi = 0; mi < 2; mi++)
        #pragma unroll
        for (int nj = 0; nj < 8; nj++)
            #pragma unroll
            for (int e = 0; e < 4; e++) acc[mi][nj][e] = 0.0f;

    // gmem->smem coords: 128 rows x 4 uint4/row = 512 copies; 2 per thread
    int lr[2], lu[2]; unsigned ldst[2]; unsigned bs[2]; int brow[2];
    #pragma unroll
    for (int i = 0; i < 2; i++) {
        int idx = tid + 256 * i;
        lr[i] = idx >> 2;                 // 0..127
        lu[i] = (idx & 3) * 4;            // word col 0,4,8,12
        ldst[i] = (unsigned)(lr[i] * (GSTR * 4) + lu[i] * 4);
        bool ok = (bn + lr[i]) < N;
        bs[i] = ok ? 16u : 0u;            // cp.async src-size (0 => zero-fill)
        brow[i] = ok ? (bn + lr[i]) : (N - 1);
    }

    // ldmatrix per-lane byte offsets within one matrix buffer
    unsigned aoffA = (unsigned)((wm + (lane & 15)) * (GSTR * 4) + (lane >> 4) * 16);
    unsigned aoffB = (unsigned)((wn + (lane >> 4) * 8 + (lane & 7)) * (GSTR * 4)
                                + ((lane >> 3) & 1) * 16);

    // ---- prologue: stage 0 loads ----
    #pragma unroll
    for (int i = 0; i < 2; i++) {
        size_t ao = (size_t)(bm + lr[i]) * K2 + lu[i];
        size_t bo = (size_t)brow[i] * K2 + lu[i];
        unsigned d = sb + ldst[i];
        cp16(d + 0 * GMAT, A_h + ao, 16u);
        cp16(d + 1 * GMAT, A_l + ao, 16u);
        cp16(d + 2 * GMAT, B_h + bo, bs[i]);
        cp16(d + 3 * GMAT, B_l + bo, bs[i]);
    }
    cp_commit();

    int S = K2 / 16;
    for (int s = 0; s < S; s++) {
        int st = s & 1;
        int k1 = (s + 1) * 16;
        if (k1 < K2) {
            unsigned base = sb + (st ^ 1) * GSTAGE;
            #pragma unroll
            for (int i = 0; i < 2; i++) {
                size_t ao = (size_t)(bm + lr[i]) * K2 + k1 + lu[i];
                size_t bo = (size_t)brow[i] * K2 + k1 + lu[i];
                unsigned d = base + ldst[i];
                cp16(d + 0 * GMAT, A_h + ao, 16u);
                cp16(d + 1 * GMAT, A_l + ao, 16u);
                cp16(d + 2 * GMAT, B_h + bo, bs[i]);
                cp16(d + 3 * GMAT, B_l + bo, bs[i]);
            }
        }
        cp_commit();
        cp_wait1();            // current stage's group complete
        __syncthreads();

        unsigned aH = sb + st * GSTAGE + 0 * GMAT + aoffA;
        unsigned aL = sb + st * GSTAGE + 1 * GMAT + aoffA;
        unsigned bH = sb + st * GSTAGE + 2 * GMAT + aoffB;
        unsigned bL = sb + st * GSTAGE + 3 * GMAT + aoffB;

        #pragma unroll
        for (int ch = 0; ch < 2; ch++) {
            unsigned kb = (unsigned)(ch * 8 * 4);   // k-chunk byte offset
            unsigned ah2[2][4], al2[2][4];
            #pragma unroll
            for (int mi = 0; mi < 2; mi++) {
                unsigned off = (unsigned)(mi * 16 * GSTR * 4) + kb;
                ldsm4(ah2[mi], aH + off);
                ldsm4(al2[mi], aL + off);
            }
            #pragma unroll
            for (int njp = 0; njp < 4; njp++) {
                unsigned off = (unsigned)(njp * 16 * GSTR * 4) + kb;
                unsigned bh4[4], bl4[4];
                ldsm4(bh4, bH + off);
                ldsm4(bl4, bL + off);
                #pragma unroll
                for (int half = 0; half < 2; half++) {
                    int nj = njp * 2 + half;
                    #pragma unroll
                    for (int mi = 0; mi < 2; mi++) {
                        mma_bf16(acc[mi][nj], ah2[mi], bh4 + 2 * half);
                        mma_bf16(acc[mi][nj], ah2[mi], bl4 + 2 * half);
                        mma_bf16(acc[mi][nj], al2[mi], bh4 + 2 * half);
                    }
                }
            }
        }
        __syncthreads();       // all reads of stage st done before reuse
    }

    // ---- epilogue: c0:(g,2t4) c1:(g,2t4+1) c2:(g+8,2t4) c3:(g+8,2t4+1) ----
    #pragma unroll
    for (int mi = 0; mi < 2; mi++) {
        int rr = bm + wm + mi * 16 + g;
        #pragma unroll
        for (int nj = 0; nj < 8; nj++) {
            int cb = bn + wn + nj * 8 + 2 * t4;
            #pragma unroll
            for (int e = 0; e < 4; e++) {
                int row = rr + (e >> 1) * 8;
                int col = cb + (e & 1);
                if (col < N) {
                    float v = acc[mi][nj][e];
                    if (bias) v += bias[col];
                    size_t idx = (size_t)row * N + col;
                    if (EPI == 1) v = gelu_f(v);
                    if (EPI == 2) v += C[idx];
                    C[idx] = v;
                }
            }
        }
    }
}

// ---------------- attention: scores = Q K^T * scale (mma, 64x64 tile) ----
__global__ __launch_bounds__(256) void qk_kernel(
    const float* __restrict__ qkv, float* __restrict__ att)
{
    int kt = blockIdx.x, qt = blockIdx.y, bh = blockIdx.z;
    if (kt > qt) return;
    int b = bh / HEADS, h = bh - b * HEADS;

    __shared__ unsigned Qh[64][36], Ql[64][36];
    __shared__ unsigned Kh[64][36], Kl[64][36];

    int tid  = threadIdx.x;
    int lane = tid & 31;
    int wid  = tid >> 5;
    int g    = lane >> 2;
    int t4   = lane & 3;
    int wm   = (wid & 1) * 32;
    int wn   = (wid >> 1) * 16;

    const float* qb = qkv + (size_t)(b * SEQ + qt * 64) * E3 + h * DHEAD;
    const float* kb = qkv + (size_t)(b * SEQ + kt * 64) * E3 + EMB + h * DHEAD;

    #pragma unroll
    for (int i = 0; i < 4; i++) {
        int idx = tid + 256 * i;
        int r = idx >> 4;
        int d = (idx & 15) * 4;
        int w = d >> 1;
        unsigned h0, l0, h1, l1;
        float4 qv = *(const float4*)(qb + (size_t)r * E3 + d);
        split2(qv.x, qv.y, h0, l0); split2(qv.z, qv.w, h1, l1);
        Qh[r][w] = h0; Qh[r][w + 1] = h1;
        Ql[r][w] = l0; Ql[r][w + 1] = l1;
        float4 kv = *(const float4*)(kb + (size_t)r * E3 + d);
        split2(kv.x, kv.y, h0, l0); split2(kv.z, kv.w, h1, l1);
        Kh[r][w] = h0; Kh[r][w + 1] = h1;
        Kl[r][w] = l0; Kl[r][w + 1] = l1;
    }
    __syncthreads();

    float acc[2][2][4];
    #pragma unroll
    for (int mi = 0; mi < 2; mi++)
        #pragma unroll
        for (int nj = 0; nj < 2; nj++)
            #pragma unroll
            for (int e = 0; e < 4; e++) acc[mi][nj][e] = 0.0f;

    #pragma unroll
    for (int ch = 0; ch < 4; ch++) {
        int kc = ch * 8;
        unsigned ah[2][4], al[2][4];
        #pragma unroll
        for (int mi = 0; mi < 2; mi++) {
            int m = wm + mi * 16 + g;
            ah[mi][0] = Qh[m    ][kc + t4];
            ah[mi][1] = Qh[m + 8][kc + t4];
            ah[mi][2] = Qh[m    ][kc + t4 + 4];
            ah[mi][3] = Qh[m + 8][kc + t4 + 4];
            al[mi][0] = Ql[m    ][kc + t4];
            al[mi][1] = Ql[m + 8][kc + t4];
            al[mi][2] = Ql[m    ][kc + t4 + 4];
            al[mi][3] = Ql[m + 8][kc + t4 + 4];
        }
        #pragma unroll
        for (int nj = 0; nj < 2; nj++) {
            int n = wn + nj * 8 + g;
            unsigned bh[2] = { Kh[n][kc + t4], Kh[n][kc + t4 + 4] };
            unsigned bl[2] = { Kl[n][kc + t4], Kl[n][kc + t4 + 4] };
            #pragma unroll
            for (int mi = 0; mi < 2; mi++) {
                mma_bf16(acc[mi][nj], ah[mi], bh);
                mma_bf16(acc[mi][nj], ah[mi], bl);
                mma_bf16(acc[mi][nj], al[mi], bh);
            }
        }
    }

    const float scale = 0.125f;
    #pragma unroll
    for (int mi = 0; mi < 2; mi++) {
        #pragma unroll
        for (int nj = 0; nj < 2; nj++) {
            #pragma unroll
            for (int e = 0; e < 4; e++) {
                int row = qt * 64 + wm + mi * 16 + g + (e >> 1) * 8;
                int col = kt * 64 + wn + nj * 8 + 2 * t4 + (e & 1);
                att[((size_t)bh * SEQ + row) * SEQ + col] = acc[mi][nj][e] * scale;
            }
        }
    }
}

// ---------------- causal row softmax ----------------
__global__ __launch_bounds__(256) void softmax_kernel(float* __restrict__ att)
{
    __shared__ float red[8];
    int q = blockIdx.x, bh = blockIdx.y;
    float* row = att + ((size_t)bh * SEQ + q) * SEQ;
    int n = q + 1;
    int tid = threadIdx.x;

    float m = -3.0e38f;
    for (int j = tid; j < n; j += 256) m = fmaxf(m, row[j]);
    m = block_max(m, red);

    float s = 0.0f;
    for (int j = tid; j < n; j += 256) {
        float e = __expf(row[j] - m);
        row[j] = e;
        s += e;
    }
    s = block_sum(s, red);
    float inv = 1.0f / s;

    for (int j = tid; j < SEQ; j += 256)
        row[j] = (j < n) ? row[j] * inv : 0.0f;
}

// ---------------- attention: Y = P @ V (mma, 64x64 tiles over k) ---------
__global__ __launch_bounds__(256) void av_kernel(
    const float* __restrict__ att, const float* __restrict__ qkv,
    float* __restrict__ y)
{
    int qt = blockIdx.x, bh = blockIdx.y;
    int b = bh / HEADS, h = bh - b * HEADS;

    __shared__ unsigned Ph[64][36], Pl[64][36];
    __shared__ unsigned Vh[32][72], Vl[32][72];

    int tid  = threadIdx.x;
    int lane = tid & 31;
    int wid  = tid >> 5;
    int g    = lane >> 2;
    int t4   = lane & 3;
    int wm   = (wid & 1) * 32;
    int wn   = (wid >> 1) * 16;

    float acc[2][2][4];
    #pragma unroll
    for (int mi = 0; mi < 2; mi++)
        #pragma unroll
        for (int nj = 0; nj < 2; nj++)
            #pragma unroll
            for (int e = 0; e < 4; e++) acc[mi][nj][e] = 0.0f;

    const float* prow = att + ((size_t)bh * SEQ + qt * 64) * SEQ;
    const float* vbase = qkv + (size_t)(b * SEQ) * E3 + 2 * EMB + h * DHEAD;

    for (int kt = 0; kt <= qt; kt++) {
        #pragma unroll
        for (int i = 0; i < 4; i++) {
            int idx = tid + 256 * i;
            int r = idx >> 4;
            int ck = (idx & 15) * 4;
            int w = ck >> 1;
            float4 pv = *(const float4*)(prow + (size_t)r * SEQ + kt * 64 + ck);
            unsigned h0, l0, h1, l1;
            split2(pv.x, pv.y, h0, l0); split2(pv.z, pv.w, h1, l1);
            Ph[r][w] = h0; Ph[r][w + 1] = h1;
            Pl[r][w] = l0; Pl[r][w + 1] = l1;
        }
        #pragma unroll
        for (int i = 0; i < 2; i++) {
            int idx = tid + 256 * i;
            int kp = idx >> 4;
            int c  = (idx & 15) * 4;
            const float* v0p = vbase + (size_t)(kt * 64 + 2 * kp) * E3 + c;
            float4 v0 = *(const float4*)(v0p);
            float4 v1 = *(const float4*)(v0p + E3);
            unsigned hw, lw;
            split2(v0.x, v1.x, hw, lw); Vh[kp][c]     = hw; Vl[kp][c]     = lw;
            split2(v0.y, v1.y, hw, lw); Vh[kp][c + 1] = hw; Vl[kp][c + 1] = lw;
            split2(v0.z, v1.z, hw, lw); Vh[kp][c + 2] = hw; Vl[kp][c + 2] = lw;
            split2(v0.w, v1.w, hw, lw); Vh[kp][c + 3] = hw; Vl[kp][c + 3] = lw;
        }
        __syncthreads();

        #pragma unroll
        for (int ch = 0; ch < 4; ch++) {
            int kc = ch * 8;
            unsigned ah[2][4], al[2][4];
            #pragma unroll
            for (int mi = 0; mi < 2; mi++) {
                int m = wm + mi * 16 + g;
                ah[mi][0] = Ph[m    ][kc + t4];
                ah[mi][1] = Ph[m + 8][kc + t4];
                ah[mi][2] = Ph[m    ][kc + t4 + 4];
                ah[mi][3] = Ph[m + 8][kc + t4 + 4];
                al[mi][0] = Pl[m    ][kc + t4];
                al[mi][1] = Pl[m + 8][kc + t4];
                al[mi][2] = Pl[m    ][kc + t4 + 4];
                al[mi][3] = Pl[m + 8][kc + t4 + 4];
            }
            #pragma unroll
            for (int nj = 0; nj < 2; nj++) {
                int n = wn + nj * 8 + g;
                unsigned bh2[2] = { Vh[kc + t4][n], Vh[kc + t4 + 4][n] };
                unsigned bl2[2] = { Vl[kc + t4][n], Vl[kc + t4 + 4][n] };
                #pragma unroll
                for (int mi = 0; mi < 2; mi++) {
                    mma_bf16(acc[mi][nj], ah[mi], bh2);
                    mma_bf16(acc[mi][nj], ah[mi], bl2);
                    mma_bf16(acc[mi][nj], al[mi], bh2);
                }
            }
        }
        __syncthreads();
    }

    #pragma unroll
    for (int mi = 0; mi < 2; mi++) {
        #pragma unroll
        for (int nj = 0; nj < 2; nj++) {
            #pragma unroll
            for (int e = 0; e < 4; e++) {
                int row = qt * 64 + wm + mi * 16 + g + (e >> 1) * 8;
                int col = wn + nj * 8 + 2 * t4 + (e & 1);
                y[(size_t)(b * SEQ + row) * EMB + h * DHEAD + col] = acc[mi][nj][e];
            }
        }
    }
}

// ---------------- launch ----------------
static inline int cdiv(size_t a, int b) { return (int)((a + b - 1) / b); }

extern "C" void kernel_launch(void* const* d_in, const int* in_sizes, int n_in,
                              void* d_out, int out_size)
{
    const int*   x    = (const int*)  d_in[0];
    const float* wte  = (const float*)d_in[1];
    const float* wpe  = (const float*)d_in[2];
    const float* ln1g = (const float*)d_in[3];
    const float* ln1b = (const float*)d_in[4];
    const float* attw = (const float*)d_in[5];
    const float* attb = (const float*)d_in[6];
    const float* apw  = (const float*)d_in[7];
    const float* apb  = (const float*)d_in[8];
    const float* ln2g = (const float*)d_in[9];
    const float* ln2b = (const float*)d_in[10];
    const float* fcw  = (const float*)d_in[11];
    const float* fcb  = (const float*)d_in[12];
    const float* fpw  = (const float*)d_in[13];
    const float* fpb  = (const float*)d_in[14];
    const float* lnfg = (const float*)d_in[15];
    const float* lnfb = (const float*)d_in[16];
    const float* lmw  = (const float*)d_in[17];
    float* out = (float*)d_out;

    float *h, *a, *yb, *qkv, *att, *fc;
    unsigned *wqh, *wql, *waph, *wapl, *wfch, *wfcl, *wfph, *wfpl, *wlmh, *wlml;
    unsigned *ah, *al;
    cudaGetSymbolAddress((void**)&h,    g_h);
    cudaGetSymbolAddress((void**)&a,    g_a);
    cudaGetSymbolAddress((void**)&yb,   g_y);
    cudaGetSymbolAddress((void**)&qkv,  g_qkv);
    cudaGetSymbolAddress((void**)&att,  g_att);
    cudaGetSymbolAddress((void**)&fc,   g_fc);
    cudaGetSymbolAddress((void**)&wqh,  g_wqkv_h);
    cudaGetSymbolAddress((void**)&wql,  g_wqkv_l);
    cudaGetSymbolAddress((void**)&waph, g_wap_h);
    cudaGetSymbolAddress((void**)&wapl, g_wap_l);
    cudaGetSymbolAddress((void**)&wfch, g_wfc_h);
    cudaGetSymbolAddress((void**)&wfcl, g_wfc_l);
    cudaGetSymbolAddress((void**)&wfph, g_wfp_h);
    cudaGetSymbolAddress((void**)&wfpl, g_wfp_l);
    cudaGetSymbolAddress((void**)&wlmh, g_wlm_h);
    cudaGetSymbolAddress((void**)&wlml, g_wlm_l);
    cudaGetSymbolAddress((void**)&ah,   g_ah);
    cudaGetSymbolAddress((void**)&al,   g_al);

    cudaFuncSetAttribute(mma_gemm_kernel<0>,
        cudaFuncAttributeMaxDynamicSharedMemorySize, GSMEM);
    cudaFuncSetAttribute(mma_gemm_kernel<1>,
        cudaFuncAttributeMaxDynamicSharedMemorySize, GSMEM);
    cudaFuncSetAttribute(mma_gemm_kernel<2>,
        cudaFuncAttributeMaxDynamicSharedMemorySize, GSMEM);

    embed_kernel<<<(TOK * EMB + 255) / 256, 256>>>(x, wte, wpe, h);

    // ---- pre-split + transpose all weights (once per launch) ----
    wsplitT_kernel<<<dim3(KW / 32, E3 / 32, LAYERS), 256>>>(
        attw, wqh, wql, KW, E3, (size_t)EMB * E3, (size_t)E3 * KW);
    wsplitT_kernel<<<dim3(KW / 32, EMB / 32, LAYERS), 256>>>(
        apw, waph, wapl, KW, EMB, (size_t)EMB * EMB, (size_t)EMB * KW);
    wsplitT_kernel<<<dim3(KW / 32, E4 / 32, LAYERS), 256>>>(
        fcw, wfch, wfcl, KW, E4, (size_t)EMB * E4, (size_t)E4 * KW);
    wsplitT_kernel<<<dim3(KW4 / 32, EMB / 32, LAYERS), 256>>>(
        fpw, wfph, wfpl, KW4, EMB, (size_t)E4 * EMB, (size_t)EMB * KW4);
    wsplitT_kernel<<<dim3(KW / 32, cdiv(VOCAB, 32), 1), 256>>>(
        lmw, wlmh, wlml, KW, VOCAB, 0, 0);

    for (int l = 0; l < LAYERS; l++) {
        ln_kernel<<<TOK, 256>>>(h, ln1g + l * EMB, ln1b + l * EMB, a);
        asplit_kernel<<<cdiv((size_t)TOK * KW, 256), 256>>>(a, ah, al, TOK * KW);
        mma_gemm_kernel<0><<<dim3(E3 / 128, TOK / 128), 256, GSMEM>>>(
            ah, al, wqh + (size_t)l * E3 * KW, wql + (size_t)l * E3 * KW,
            attb + (size_t)l * E3, qkv, TOK, E3, KW);

        qk_kernel<<<dim3(SEQ / 64, SEQ / 64, BATCH * HEADS), 256>>>(qkv, att);
        softmax_kernel<<<dim3(SEQ, BATCH * HEADS), 256>>>(att);
        av_kernel<<<dim3(SEQ / 64, BATCH * HEADS), 256>>>(att, qkv, yb);

        asplit_kernel<<<cdiv((size_t)TOK * KW, 256), 256>>>(yb, ah, al, TOK * KW);
        mma_gemm_kernel<2><<<dim3(EMB / 128, TOK / 128), 256, GSMEM>>>(
            ah, al, waph + (size_t)l * EMB * KW, wapl + (size_t)l * EMB * KW,
            apb + (size_t)l * EMB, h, TOK, EMB, KW);

        ln_kernel<<<TOK, 256>>>(h, ln2g + l * EMB, ln2b + l * EMB, a);
        asplit_kernel<<<cdiv((size_t)TOK * KW, 256), 256>>>(a, ah, al, TOK * KW);
        mma_gemm_kernel<1><<<dim3(E4 / 128, TOK / 128), 256, GSMEM>>>(
            ah, al, wfch + (size_t)l * E4 * KW, wfcl + (size_t)l * E4 * KW,
            fcb + (size_t)l * E4, fc, TOK, E4, KW);

        asplit_kernel<<<cdiv((size_t)TOK * KW4, 256), 256>>>(fc, ah, al, TOK * KW4);
        mma_gemm_kernel<2><<<dim3(EMB / 128, TOK / 128), 256, GSMEM>>>(
            ah, al, wfph + (size_t)l * EMB * KW4, wfpl + (size_t)l * EMB * KW4,
            fpb + (size_t)l * EMB, h, TOK, EMB, KW4);
    }

    ln_kernel<<<TOK, 256>>>(h, lnfg, lnfb, a);
    asplit_kernel<<<cdiv((size_t)TOK * KW, 256), 256>>>(a, ah, al, TOK * KW);
    mma_gemm_kernel<0><<<dim3(cdiv(VOCAB, 128), TOK / 128), 256, GSMEM>>>(
        ah, al, wlmh, wlml, nullptr, out, TOK, VOCAB, KW);
}

// round 15
// speedup vs baseline: 1.1421x; 1.1421x over previous
#include <cuda_runtime.h>
#include <cuda_bf16.h>
#include <math.h>

// ---------------- constants ----------------
#define LAYERS 12
#define HEADS  12
#define EMB    768
#define DHEAD  64
#define VOCAB  50257
#define BATCH  4
#define SEQ    1024
#define TOK    (BATCH * SEQ)          // 4096
#define E3     (3 * EMB)              // 2304
#define E4     (4 * EMB)              // 3072
#define KW     (EMB / 2)              // 384 words (k-pairs) for K=768
#define KW4    (E4 / 2)               // 1536 words for K=3072

// ---------------- scratch (__device__ globals: no cudaMalloc allowed) ------
__device__ float g_h  [(size_t)TOK * EMB];
__device__ float g_a  [(size_t)TOK * EMB];
__device__ float g_y  [(size_t)TOK * EMB];
__device__ float g_qkv[(size_t)TOK * E3];
__device__ float g_fc [(size_t)TOK * E4];

// pre-split weights, TRANSPOSED: [N][K2] packed bf16x2 hi/lo words
__device__ unsigned g_wqkv_h[(size_t)LAYERS * E3 * KW];
__device__ unsigned g_wqkv_l[(size_t)LAYERS * E3 * KW];
__device__ unsigned g_wap_h [(size_t)LAYERS * EMB * KW];
__device__ unsigned g_wap_l [(size_t)LAYERS * EMB * KW];
__device__ unsigned g_wfc_h [(size_t)LAYERS * E4 * KW];
__device__ unsigned g_wfc_l [(size_t)LAYERS * E4 * KW];
__device__ unsigned g_wfp_h [(size_t)LAYERS * EMB * KW4];
__device__ unsigned g_wfp_l [(size_t)LAYERS * EMB * KW4];
__device__ unsigned g_wlm_h [(size_t)VOCAB * KW];
__device__ unsigned g_wlm_l [(size_t)VOCAB * KW];
// pre-split activations (reused per GEMM; sized for largest A = TOK x E4)
__device__ unsigned g_ah[(size_t)TOK * KW4];
__device__ unsigned g_al[(size_t)TOK * KW4];

// ---------------- helpers ----------------
__device__ __forceinline__ float gelu_f(float x) {
    float x3 = x * x * x;
    return 0.5f * x * (1.0f + tanhf(0.7978845608028654f * (x + 0.044715f * x3)));
}

// split two consecutive-k floats into packed bf16x2 hi and lo words
__device__ __forceinline__ void split2(float f0, float f1,
                                       unsigned& hi, unsigned& lo) {
    __nv_bfloat16 h0 = __float2bfloat16(f0);
    __nv_bfloat16 h1 = __float2bfloat16(f1);
    __nv_bfloat16 l0 = __float2bfloat16(f0 - __bfloat162float(h0));
    __nv_bfloat16 l1 = __float2bfloat16(f1 - __bfloat162float(h1));
    hi = ((unsigned)__bfloat16_as_ushort(h1) << 16) | __bfloat16_as_ushort(h0);
    lo = ((unsigned)__bfloat16_as_ushort(l1) << 16) | __bfloat16_as_ushort(l0);
}

// D += A*B  (m16n8k16 bf16, row.col, fp32 accum)
__device__ __forceinline__ void mma_bf16(float* c, const unsigned* a, const unsigned* b) {
    asm volatile(
        "mma.sync.aligned.m16n8k16.row.col.f32.bf16.bf16.f32 "
        "{%0,%1,%2,%3}, {%4,%5,%6,%7}, {%8,%9}, {%0,%1,%2,%3};\n"
        : "+f"(c[0]), "+f"(c[1]), "+f"(c[2]), "+f"(c[3])
        : "r"(a[0]), "r"(a[1]), "r"(a[2]), "r"(a[3]),
          "r"(b[0]), "r"(b[1]));
}

__device__ __forceinline__ void ldsm4(unsigned* r, unsigned addr) {
    asm volatile("ldmatrix.sync.aligned.m8n8.x4.shared.b16 {%0,%1,%2,%3}, [%4];"
        : "=r"(r[0]), "=r"(r[1]), "=r"(r[2]), "=r"(r[3]) : "r"(addr));
}

__device__ __forceinline__ unsigned cvta_s(const void* p) {
    return (unsigned)__cvta_generic_to_shared(p);
}

__device__ __forceinline__ float warp_sum(float v) {
    #pragma unroll
    for (int o = 16; o > 0; o >>= 1) v += __shfl_xor_sync(0xffffffffu, v, o);
    return v;
}
__device__ __forceinline__ float block_sum(float v, float* sm) {
    v = warp_sum(v);
    int w = threadIdx.x >> 5, l = threadIdx.x & 31;
    if (l == 0) sm[w] = v;
    __syncthreads();
    float r = (l < 8) ? sm[l] : 0.0f;
    r = warp_sum(r);
    __syncthreads();
    return r;
}

// ---------------- weight split + transpose (once per launch) --------------
__global__ __launch_bounds__(256) void wsplitT_kernel(
    const float* __restrict__ W, unsigned* __restrict__ hi,
    unsigned* __restrict__ lo, int K2, int N,
    size_t wstride, size_t ostride)
{
    __shared__ float s0[32][33], s1[32][33];
    const float* Wl = W + (size_t)blockIdx.z * wstride;
    int kp0 = blockIdx.x * 32;
    int n0  = blockIdx.y * 32;
    int tx = threadIdx.x & 31, ty = threadIdx.x >> 5;
    #pragma unroll
    for (int i = ty; i < 32; i += 8) {
        int kp = kp0 + i;
        int n = n0 + tx;
        float v0 = 0.0f, v1 = 0.0f;
        if (n < N) {
            v0 = Wl[(size_t)(2 * kp) * N + n];
            v1 = Wl[(size_t)(2 * kp + 1) * N + n];
        }
        s0[i][tx] = v0; s1[i][tx] = v1;
    }
    __syncthreads();
    unsigned* hil = hi + (size_t)blockIdx.z * ostride;
    unsigned* lol = lo + (size_t)blockIdx.z * ostride;
    #pragma unroll
    for (int i = ty; i < 32; i += 8) {
        int n = n0 + i;
        if (n < N) {
            unsigned h, l;
            split2(s0[tx][i], s1[tx][i], h, l);
            hil[(size_t)n * K2 + kp0 + tx] = h;
            lol[(size_t)n * K2 + kp0 + tx] = l;
        }
    }
}

// activations: A[M,K] fp32 (pairs contiguous along K) -> hi/lo words
__global__ __launch_bounds__(256) void asplit_kernel(
    const float* __restrict__ A, unsigned* __restrict__ hi,
    unsigned* __restrict__ lo, int total_words)
{
    int idx = blockIdx.x * 256 + threadIdx.x;
    if (idx < total_words) {
        float2 v = ((const float2*)A)[idx];
        unsigned h, l;
        split2(v.x, v.y, h, l);
        hi[idx] = h; lo[idx] = l;
    }
}

// ---------------- embedding ----------------
__global__ __launch_bounds__(256) void embed_kernel(
    const int* __restrict__ x, const float* __restrict__ wte,
    const float* __restrict__ wpe, float* __restrict__ h)
{
    int i = blockIdx.x * 256 + threadIdx.x;
    if (i < TOK * EMB) {
        int t = i / EMB;
        int e = i - t * EMB;
        int s = t & (SEQ - 1);
        h[i] = wte[(size_t)x[t] * EMB + e] + wpe[(size_t)s * EMB + e];
    }
}

// ---------------- layernorm (row = 768) ----------------
__global__ __launch_bounds__(256) void ln_kernel(
    const float* __restrict__ x, const float* __restrict__ g,
    const float* __restrict__ b, float* __restrict__ y)
{
    __shared__ float red[8];
    int row = blockIdx.x;
    const float* xr = x + (size_t)row * EMB;
    int tid = threadIdx.x;
    float v0 = xr[tid], v1 = xr[tid + 256], v2 = xr[tid + 512];
    float s  = v0 + v1 + v2;
    float s2 = v0 * v0 + v1 * v1 + v2 * v2;
    s  = block_sum(s,  red);
    __syncthreads();
    s2 = block_sum(s2, red);
    float mean = s * (1.0f / EMB);
    float var  = s2 * (1.0f / EMB) - mean * mean;
    float inv  = rsqrtf(var + 1e-5f);
    float* yr = y + (size_t)row * EMB;
    yr[tid]       = (v0 - mean) * inv * g[tid]       + b[tid];
    yr[tid + 256] = (v1 - mean) * inv * g[tid + 256] + b[tid + 256];
    yr[tid + 512] = (v2 - mean) * inv * g[tid + 512] + b[tid + 512];
}

// ---------------- split-bf16 tensor-core GEMM (ldmatrix, reg prefetch) ----
// C[M,N] = A[M,K] @ B^T (B stored [N][K2] n-major). EPI: 0=write 1=gelu 2=resid.
// Both operands pre-split packed bf16x2 hi/lo words [rows][K2].
// Block tile 128x128, k-tile 16 words (32 k), register double-buffered.
// 8 warps 4(m) x 2(n); warp tile 32x64 = 2 x 8 m16n8k16 fragments.
// Smem [128][20]: stride 20 -> every ldmatrix 8-row phase hits 32 distinct banks.
template <int EPI>
__global__ __launch_bounds__(256) void mma_gemm_kernel(
    const unsigned* __restrict__ A_h, const unsigned* __restrict__ A_l,
    const unsigned* __restrict__ B_h, const unsigned* __restrict__ B_l,
    const float* __restrict__ bias, float* __restrict__ C,
    int M, int N, int K2)
{
    __shared__ unsigned Ah[128][20], Al[128][20];
    __shared__ unsigned Bh[128][20], Bl[128][20];

    int tid  = threadIdx.x;
    int lane = tid & 31;
    int wid  = tid >> 5;
    int g    = lane >> 2;      // 0..7
    int t4   = lane & 3;       // 0..3
    int wm   = (wid & 3) * 32;
    int wn   = (wid >> 2) * 64;

    int bm = blockIdx.y * 128;
    int bn = blockIdx.x * 128;

    float acc[2][8][4];
    #pragma unroll
    for (int mi = 0; mi < 2; mi++)
        #pragma unroll
        for (int nj = 0; nj < 8; nj++)
            #pragma unroll
            for (int e = 0; e < 4; e++) acc[mi][nj][e] = 0.0f;

    // ldmatrix per-lane base addresses
    unsigned aBH = cvta_s(&Ah[wm + (lane & 15)][(lane >> 4) * 4]);
    unsigned aBL = cvta_s(&Al[wm + (lane & 15)][(lane >> 4) * 4]);
    unsigned bBH = cvta_s(&Bh[wn + ((lane >> 4) * 8) + (lane & 7)][((lane >> 3) & 1) * 4]);
    unsigned bBL = cvta_s(&Bl[wn + ((lane >> 4) * 8) + (lane & 7)][((lane >> 3) & 1) * 4]);

    // gmem load coords: 128 rows x 16 words = 512 uint4; 2 per thread
    int r[2], c[2];
    bool okB[2];
    #pragma unroll
    for (int i = 0; i < 2; i++) {
        int idx = tid + 256 * i;
        r[i] = idx >> 2;              // 0..127
        c[i] = (idx & 3) * 4;         // 0,4,8,12
        okB[i] = (bn + r[i]) < N;
    }

    uint4 sah[2], sal[2], sbh[2], sbl[2];
    const uint4 zero4 = make_uint4(0, 0, 0, 0);

    // ---- prologue loads (k-tile 0) ----
    #pragma unroll
    for (int i = 0; i < 2; i++) {
        size_t ao = (size_t)(bm + r[i]) * K2 + c[i];
        sah[i] = *(const uint4*)(A_h + ao);
        sal[i] = *(const uint4*)(A_l + ao);
        size_t bo = (size_t)(bn + r[i]) * K2 + c[i];
        sbh[i] = okB[i] ? *(const uint4*)(B_h + bo) : zero4;
        sbl[i] = okB[i] ? *(const uint4*)(B_l + bo) : zero4;
    }

    for (int k0 = 0; k0 < K2; k0 += 16) {
        // ---- store stage -> smem ----
        #pragma unroll
        for (int i = 0; i < 2; i++) {
            *(uint4*)&Ah[r[i]][c[i]] = sah[i];
            *(uint4*)&Al[r[i]][c[i]] = sal[i];
            *(uint4*)&Bh[r[i]][c[i]] = sbh[i];
            *(uint4*)&Bl[r[i]][c[i]] = sbl[i];
        }
        __syncthreads();

        // ---- prefetch next k-tile into registers ----
        int k1 = k0 + 16;
        if (k1 < K2) {
            #pragma unroll
            for (int i = 0; i < 2; i++) {
                size_t ao = (size_t)(bm + r[i]) * K2 + k1 + c[i];
                sah[i] = *(const uint4*)(A_h + ao);
                sal[i] = *(const uint4*)(A_l + ao);
                size_t bo = (size_t)(bn + r[i]) * K2 + k1 + c[i];
                sbh[i] = okB[i] ? *(const uint4*)(B_h + bo) : zero4;
                sbl[i] = okB[i] ? *(const uint4*)(B_l + bo) : zero4;
            }
        }

        // ---- mma over 2 k16 chunks ----
        #pragma unroll
        for (int ch = 0; ch < 2; ch++) {
            int kc = ch * 8;
            unsigned ah2[2][4], al2[2][4];
            #pragma unroll
            for (int mi = 0; mi < 2; mi++) {
                unsigned off = (unsigned)(mi * 16 * 20 + kc) * 4u;
                ldsm4(ah2[mi], aBH + off);
                ldsm4(al2[mi], aBL + off);
            }
            #pragma unroll
            for (int njp = 0; njp < 4; njp++) {
                unsigned off = (unsigned)(njp * 16 * 20 + kc) * 4u;
                unsigned bh4[4], bl4[4];
                ldsm4(bh4, bBH + off);
                ldsm4(bl4, bBL + off);
                #pragma unroll
                for (int half = 0; half < 2; half++) {
                    int nj = njp * 2 + half;
                    #pragma unroll
                    for (int mi = 0; mi < 2; mi++) {
                        mma_bf16(acc[mi][nj], ah2[mi], bh4 + 2 * half);
                        mma_bf16(acc[mi][nj], ah2[mi], bl4 + 2 * half);
                        mma_bf16(acc[mi][nj], al2[mi], bh4 + 2 * half);
                    }
                }
            }
        }
        __syncthreads();
    }

    // ---- epilogue: c0:(g,2t4) c1:(g,2t4+1) c2:(g+8,2t4) c3:(g+8,2t4+1) ----
    #pragma unroll
    for (int mi = 0; mi < 2; mi++) {
        int rr = bm + wm + mi * 16 + g;
        #pragma unroll
        for (int nj = 0; nj < 8; nj++) {
            int cb = bn + wn + nj * 8 + 2 * t4;
            #pragma unroll
            for (int e = 0; e < 4; e++) {
                int row = rr + (e >> 1) * 8;
                int col = cb + (e & 1);
                if (col < N) {
                    float v = acc[mi][nj][e];
                    if (bias) v += bias[col];
                    size_t idx = (size_t)row * N + col;
                    if (EPI == 1) v = gelu_f(v);
                    if (EPI == 2) v += C[idx];
                    C[idx] = v;
                }
            }
        }
    }
}

// ---------------- fused flash attention ----------------------------------
// One CTA per (b, h, 128-row q-tile). 8 warps x 16 q-rows, online softmax.
// Q split-fragments preloaded to registers; K/V tiles (64 keys) split into
// smem per iteration. P stays in registers: S-fragment C-layout == A-fragment
// layout after bf16x2 packing; hi/lo split preserved for P@V.
// Smem union (9216 words = 36 KB): Q phase Qh[128][36]+Ql; KV phase
// Kh[64][36]+Kl + Vh[32][72]+Vl.
__global__ __launch_bounds__(256) void flash_kernel(
    const float* __restrict__ qkv, float* __restrict__ y)
{
    __shared__ unsigned fsm[9216];
    int qt = blockIdx.x, bh = blockIdx.y;
    int b = bh / HEADS, h = bh - b * HEADS;
    int tid = threadIdx.x, lane = tid & 31, wid = tid >> 5;
    int g = lane >> 2, t4 = lane & 3;

    unsigned (*Qh)[36] = (unsigned(*)[36])(fsm);
    unsigned (*Ql)[36] = (unsigned(*)[36])(fsm + 4608);
    unsigned (*Kh)[36] = (unsigned(*)[36])(fsm);
    unsigned (*Kl)[36] = (unsigned(*)[36])(fsm + 2304);
    unsigned (*Vh)[72] = (unsigned(*)[72])(fsm + 4608);
    unsigned (*Vl)[72] = (unsigned(*)[72])(fsm + 6912);

    const float* qb = qkv + (size_t)(b * SEQ + qt * 128) * E3 + h * DHEAD;

    // ---- load Q tile 128x64 (split) ----
    #pragma unroll
    for (int i = 0; i < 8; i++) {
        int idx = tid + 256 * i;          // 0..2047
        int rr = idx >> 4;                // 0..127
        int d = (idx & 15) * 4;
        int w = d >> 1;
        float4 qv = *(const float4*)(qb + (size_t)rr * E3 + d);
        unsigned h0, l0, h1, l1;
        split2(qv.x, qv.y, h0, l0); split2(qv.z, qv.w, h1, l1);
        Qh[rr][w] = h0; Qh[rr][w + 1] = h1;
        Ql[rr][w] = l0; Ql[rr][w + 1] = l1;
    }
    __syncthreads();

    // ---- Q fragments to registers (row m..m+8, 4 k16 chunks) ----
    int m = wid * 16 + g;
    unsigned qh[4][4], ql[4][4];
    #pragma unroll
    for (int ch = 0; ch < 4; ch++) {
        int kc = ch * 8;
        qh[ch][0] = Qh[m][kc + t4];     qh[ch][1] = Qh[m + 8][kc + t4];
        qh[ch][2] = Qh[m][kc + t4 + 4]; qh[ch][3] = Qh[m + 8][kc + t4 + 4];
        ql[ch][0] = Ql[m][kc + t4];     ql[ch][1] = Ql[m + 8][kc + t4];
        ql[ch][2] = Ql[m][kc + t4 + 4]; ql[ch][3] = Ql[m + 8][kc + t4 + 4];
    }
    __syncthreads();   // Q region about to be overwritten by K

    float mrow[2] = { -3.0e38f, -3.0e38f };
    float lrow[2] = { 0.0f, 0.0f };
    float o[8][4];
    #pragma unroll
    for (int nj = 0; nj < 8; nj++)
        #pragma unroll
        for (int e = 0; e < 4; e++) o[nj][e] = 0.0f;

    const float* kbase = qkv + (size_t)(b * SEQ) * E3 + EMB + h * DHEAD;
    const float* vbase = qkv + (size_t)(b * SEQ) * E3 + 2 * EMB + h * DHEAD;
    int row0 = qt * 128 + m;

    int ktmax = 2 * qt + 1;
    for (int kt = 0; kt <= ktmax; kt++) {
        // ---- load K tile (64 keys x 64 d, split) ----
        #pragma unroll
        for (int i = 0; i < 4; i++) {
            int idx = tid + 256 * i;
            int rr = idx >> 4;            // 0..63
            int d = (idx & 15) * 4;
            int w = d >> 1;
            float4 kv = *(const float4*)(kbase + (size_t)(kt * 64 + rr) * E3 + d);
            unsigned h0, l0, h1, l1;
            split2(kv.x, kv.y, h0, l0); split2(kv.z, kv.w, h1, l1);
            Kh[rr][w] = h0; Kh[rr][w + 1] = h1;
            Kl[rr][w] = l0; Kl[rr][w + 1] = l1;
        }
        // ---- load V tile (64 keys packed in pairs along k) ----
        #pragma unroll
        for (int i = 0; i < 2; i++) {
            int idx = tid + 256 * i;
            int kp = idx >> 4;            // 0..31
            int cc = (idx & 15) * 4;
            const float* v0p = vbase + (size_t)(kt * 64 + 2 * kp) * E3 + cc;
            float4 v0 = *(const float4*)(v0p);
            float4 v1 = *(const float4*)(v0p + E3);
            unsigned hw, lw;
            split2(v0.x, v1.x, hw, lw); Vh[kp][cc]     = hw; Vl[kp][cc]     = lw;
            split2(v0.y, v1.y, hw, lw); Vh[kp][cc + 1] = hw; Vl[kp][cc + 1] = lw;
            split2(v0.z, v1.z, hw, lw); Vh[kp][cc + 2] = hw; Vl[kp][cc + 2] = lw;
            split2(v0.w, v1.w, hw, lw); Vh[kp][cc + 3] = hw; Vl[kp][cc + 3] = lw;
        }
        __syncthreads();

        // ---- S = Q K^T (warp: 16 q-rows x 64 keys) ----
        float s[8][4];
        #pragma unroll
        for (int nj = 0; nj < 8; nj++)
            #pragma unroll
            for (int e = 0; e < 4; e++) s[nj][e] = 0.0f;
        #pragma unroll
        for (int ch = 0; ch < 4; ch++) {
            int kc = ch * 8;
            #pragma unroll
            for (int nj = 0; nj < 8; nj++) {
                int n = nj * 8 + g;
                unsigned bhf[2] = { Kh[n][kc + t4], Kh[n][kc + t4 + 4] };
                unsigned blf[2] = { Kl[n][kc + t4], Kl[n][kc + t4 + 4] };
                mma_bf16(s[nj], qh[ch], bhf);
                mma_bf16(s[nj], qh[ch], blf);
                mma_bf16(s[nj], ql[ch], bhf);
            }
        }

        // ---- scale + causal mask ----
        #pragma unroll
        for (int nj = 0; nj < 8; nj++)
            #pragma unroll
            for (int e = 0; e < 4; e++) {
                int col = kt * 64 + nj * 8 + 2 * t4 + (e & 1);
                int row = row0 + (e >> 1) * 8;
                s[nj][e] = (col <= row) ? s[nj][e] * 0.125f : -3.0e38f;
            }

        // ---- online softmax (per row-half; t4 quad holds one row) ----
        #pragma unroll
        for (int half = 0; half < 2; half++) {
            float mx = -3.0e38f;
            #pragma unroll
            for (int nj = 0; nj < 8; nj++)
                mx = fmaxf(mx, fmaxf(s[nj][2 * half], s[nj][2 * half + 1]));
            mx = fmaxf(mx, __shfl_xor_sync(0xffffffffu, mx, 1));
            mx = fmaxf(mx, __shfl_xor_sync(0xffffffffu, mx, 2));
            float mn = fmaxf(mrow[half], mx);
            float sc = __expf(mrow[half] - mn);
            mrow[half] = mn;
            float sum = 0.0f;
            #pragma unroll
            for (int nj = 0; nj < 8; nj++) {
                float p0 = __expf(s[nj][2 * half]     - mn);
                float p1 = __expf(s[nj][2 * half + 1] - mn);
                s[nj][2 * half] = p0; s[nj][2 * half + 1] = p1;
                sum += p0 + p1;
            }
            sum += __shfl_xor_sync(0xffffffffu, sum, 1);
            sum += __shfl_xor_sync(0xffffffffu, sum, 2);
            lrow[half] = lrow[half] * sc + sum;
            #pragma unroll
            for (int nj = 0; nj < 8; nj++) {
                o[nj][2 * half]     *= sc;
                o[nj][2 * half + 1] *= sc;
            }
        }

        // ---- O += P V (P split+packed in registers) ----
        #pragma unroll
        for (int ch = 0; ch < 4; ch++) {
            unsigned ph[4], pl[4];
            split2(s[2 * ch][0],     s[2 * ch][1],     ph[0], pl[0]);
            split2(s[2 * ch][2],     s[2 * ch][3],     ph[1], pl[1]);
            split2(s[2 * ch + 1][0], s[2 * ch + 1][1], ph[2], pl[2]);
            split2(s[2 * ch + 1][2], s[2 * ch + 1][3], ph[3], pl[3]);
            int kc = ch * 8;
            #pragma unroll
            for (int njd = 0; njd < 8; njd++) {
                int n = njd * 8 + g;
                unsigned bh2[2] = { Vh[kc + t4][n], Vh[kc + t4 + 4][n] };
                unsigned bl2[2] = { Vl[kc + t4][n], Vl[kc + t4 + 4][n] };
                mma_bf16(o[njd], ph, bh2);
                mma_bf16(o[njd], ph, bl2);
                mma_bf16(o[njd], pl, bh2);
            }
        }
        __syncthreads();   // smem reads done before next kt overwrite
    }

    // ---- epilogue: normalize and store ----
    float inv0 = 1.0f / lrow[0];
    float inv1 = 1.0f / lrow[1];
    #pragma unroll
    for (int njd = 0; njd < 8; njd++)
        #pragma unroll
        for (int e = 0; e < 4; e++) {
            int half = e >> 1;
            int row = row0 + half * 8;
            int col = h * DHEAD + njd * 8 + 2 * t4 + (e & 1);
            y[(size_t)(b * SEQ + row) * EMB + col] =
                o[njd][e] * (half ? inv1 : inv0);
        }
}

// ---------------- launch ----------------
static inline int cdiv(size_t a, int b) { return (int)((a + b - 1) / b); }

extern "C" void kernel_launch(void* const* d_in, const int* in_sizes, int n_in,
                              void* d_out, int out_size)
{
    const int*   x    = (const int*)  d_in[0];
    const float* wte  = (const float*)d_in[1];
    const float* wpe  = (const float*)d_in[2];
    const float* ln1g = (const float*)d_in[3];
    const float* ln1b = (const float*)d_in[4];
    const float* attw = (const float*)d_in[5];
    const float* attb = (const float*)d_in[6];
    const float* apw  = (const float*)d_in[7];
    const float* apb  = (const float*)d_in[8];
    const float* ln2g = (const float*)d_in[9];
    const float* ln2b = (const float*)d_in[10];
    const float* fcw  = (const float*)d_in[11];
    const float* fcb  = (const float*)d_in[12];
    const float* fpw  = (const float*)d_in[13];
    const float* fpb  = (const float*)d_in[14];
    const float* lnfg = (const float*)d_in[15];
    const float* lnfb = (const float*)d_in[16];
    const float* lmw  = (const float*)d_in[17];
    float* out = (float*)d_out;

    float *h, *a, *yb, *qkv, *fc;
    unsigned *wqh, *wql, *waph, *wapl, *wfch, *wfcl, *wfph, *wfpl, *wlmh, *wlml;
    unsigned *ah, *al;
    cudaGetSymbolAddress((void**)&h,    g_h);
    cudaGetSymbolAddress((void**)&a,    g_a);
    cudaGetSymbolAddress((void**)&yb,   g_y);
    cudaGetSymbolAddress((void**)&qkv,  g_qkv);
    cudaGetSymbolAddress((void**)&fc,   g_fc);
    cudaGetSymbolAddress((void**)&wqh,  g_wqkv_h);
    cudaGetSymbolAddress((void**)&wql,  g_wqkv_l);
    cudaGetSymbolAddress((void**)&waph, g_wap_h);
    cudaGetSymbolAddress((void**)&wapl, g_wap_l);
    cudaGetSymbolAddress((void**)&wfch, g_wfc_h);
    cudaGetSymbolAddress((void**)&wfcl, g_wfc_l);
    cudaGetSymbolAddress((void**)&wfph, g_wfp_h);
    cudaGetSymbolAddress((void**)&wfpl, g_wfp_l);
    cudaGetSymbolAddress((void**)&wlmh, g_wlm_h);
    cudaGetSymbolAddress((void**)&wlml, g_wlm_l);
    cudaGetSymbolAddress((void**)&ah,   g_ah);
    cudaGetSymbolAddress((void**)&al,   g_al);

    embed_kernel<<<(TOK * EMB + 255) / 256, 256>>>(x, wte, wpe, h);

    // ---- pre-split + transpose all weights (once per launch) ----
    wsplitT_kernel<<<dim3(KW / 32, E3 / 32, LAYERS), 256>>>(
        attw, wqh, wql, KW, E3, (size_t)EMB * E3, (size_t)E3 * KW);
    wsplitT_kernel<<<dim3(KW / 32, EMB / 32, LAYERS), 256>>>(
        apw, waph, wapl, KW, EMB, (size_t)EMB * EMB, (size_t)EMB * KW);
    wsplitT_kernel<<<dim3(KW / 32, E4 / 32, LAYERS), 256>>>(
        fcw, wfch, wfcl, KW, E4, (size_t)EMB * E4, (size_t)E4 * KW);
    wsplitT_kernel<<<dim3(KW4 / 32, EMB / 32, LAYERS), 256>>>(
        fpw, wfph, wfpl, KW4, EMB, (size_t)E4 * EMB, (size_t)EMB * KW4);
    wsplitT_kernel<<<dim3(KW / 32, cdiv(VOCAB, 32), 1), 256>>>(
        lmw, wlmh, wlml, KW, VOCAB, 0, 0);

    for (int l = 0; l < LAYERS; l++) {
        ln_kernel<<<TOK, 256>>>(h, ln1g + l * EMB, ln1b + l * EMB, a);
        asplit_kernel<<<cdiv((size_t)TOK * KW, 256), 256>>>(a, ah, al, TOK * KW);
        mma_gemm_kernel<0><<<dim3(E3 / 128, TOK / 128), 256>>>(
            ah, al, wqh + (size_t)l * E3 * KW, wql + (size_t)l * E3 * KW,
            attb + (size_t)l * E3, qkv, TOK, E3, KW);

        flash_kernel<<<dim3(SEQ / 128, BATCH * HEADS), 256>>>(qkv, yb);

        asplit_kernel<<<cdiv((size_t)TOK * KW, 256), 256>>>(yb, ah, al, TOK * KW);
        mma_gemm_kernel<2><<<dim3(EMB / 128, TOK / 128), 256>>>(
            ah, al, waph + (size_t)l * EMB * KW, wapl + (size_t)l * EMB * KW,
            apb + (size_t)l * EMB, h, TOK, EMB, KW);

        ln_kernel<<<TOK, 256>>>(h, ln2g + l * EMB, ln2b + l * EMB, a);
        asplit_kernel<<<cdiv((size_t)TOK * KW, 256), 256>>>(a, ah, al, TOK * KW);
        mma_gemm_kernel<1><<<dim3(E4 / 128, TOK / 128), 256>>>(
            ah, al, wfch + (size_t)l * E4 * KW, wfcl + (size_t)l * E4 * KW,
            fcb + (size_t)l * E4, fc, TOK, E4, KW);

        asplit_kernel<<<cdiv((size_t)TOK * KW4, 256), 256>>>(fc, ah, al, TOK * KW4);
        mma_gemm_kernel<2><<<dim3(EMB / 128, TOK / 128), 256>>>(
            ah, al, wfph + (size_t)l * EMB * KW4, wfpl + (size_t)l * EMB * KW4,
            fpb + (size_t)l * EMB, h, TOK, EMB, KW4);
    }

    ln_kernel<<<TOK, 256>>>(h, lnfg, lnfb, a);
    asplit_kernel<<<cdiv((size_t)TOK * KW, 256), 256>>>(a, ah, al, TOK * KW);
    mma_gemm_kernel<0><<<dim3(cdiv(VOCAB, 128), TOK / 128), 256>>>(
        ah, al, wlmh, wlml, nullptr, out, TOK, VOCAB, KW);
}

// round 16
// speedup vs baseline: 1.1962x; 1.0474x over previous
#include <cuda_runtime.h>
#include <cuda_bf16.h>
#include <math.h>

// ---------------- constants ----------------
#define LAYERS 12
#define HEADS  12
#define EMB    768
#define DHEAD  64
#define VOCAB  50257
#define BATCH  4
#define SEQ    1024
#define TOK    (BATCH * SEQ)          // 4096
#define E3     (3 * EMB)              // 2304
#define E4     (4 * EMB)              // 3072
#define KW     (EMB / 2)              // 384 words (k-pairs) for K=768
#define KW4    (E4 / 2)               // 1536 words for K=3072

// ---------------- scratch (__device__ globals: no cudaMalloc allowed) ------
__device__ float g_h  [(size_t)TOK * EMB];
__device__ float g_qkv[(size_t)TOK * E3];

// pre-split weights, TRANSPOSED: [N][K2] packed bf16x2 hi/lo words
__device__ unsigned g_wqkv_h[(size_t)LAYERS * E3 * KW];
__device__ unsigned g_wqkv_l[(size_t)LAYERS * E3 * KW];
__device__ unsigned g_wap_h [(size_t)LAYERS * EMB * KW];
__device__ unsigned g_wap_l [(size_t)LAYERS * EMB * KW];
__device__ unsigned g_wfc_h [(size_t)LAYERS * E4 * KW];
__device__ unsigned g_wfc_l [(size_t)LAYERS * E4 * KW];
__device__ unsigned g_wfp_h [(size_t)LAYERS * EMB * KW4];
__device__ unsigned g_wfp_l [(size_t)LAYERS * EMB * KW4];
__device__ unsigned g_wlm_h [(size_t)VOCAB * KW];
__device__ unsigned g_wlm_l [(size_t)VOCAB * KW];
// split activations (producers write these directly)
__device__ unsigned g_ah[(size_t)TOK * KW];    // ln out / flash out
__device__ unsigned g_al[(size_t)TOK * KW];
__device__ unsigned g_fh[(size_t)TOK * KW4];   // fc (gelu) out
__device__ unsigned g_fl[(size_t)TOK * KW4];

// ---------------- helpers ----------------
__device__ __forceinline__ float gelu_f(float x) {
    float x3 = x * x * x;
    return 0.5f * x * (1.0f + tanhf(0.7978845608028654f * (x + 0.044715f * x3)));
}

// split two consecutive-k floats into packed bf16x2 hi and lo words
__device__ __forceinline__ void split2(float f0, float f1,
                                       unsigned& hi, unsigned& lo) {
    __nv_bfloat16 h0 = __float2bfloat16(f0);
    __nv_bfloat16 h1 = __float2bfloat16(f1);
    __nv_bfloat16 l0 = __float2bfloat16(f0 - __bfloat162float(h0));
    __nv_bfloat16 l1 = __float2bfloat16(f1 - __bfloat162float(h1));
    hi = ((unsigned)__bfloat16_as_ushort(h1) << 16) | __bfloat16_as_ushort(h0);
    lo = ((unsigned)__bfloat16_as_ushort(l1) << 16) | __bfloat16_as_ushort(l0);
}

// D += A*B  (m16n8k16 bf16, row.col, fp32 accum)
__device__ __forceinline__ void mma_bf16(float* c, const unsigned* a, const unsigned* b) {
    asm volatile(
        "mma.sync.aligned.m16n8k16.row.col.f32.bf16.bf16.f32 "
        "{%0,%1,%2,%3}, {%4,%5,%6,%7}, {%8,%9}, {%0,%1,%2,%3};\n"
        : "+f"(c[0]), "+f"(c[1]), "+f"(c[2]), "+f"(c[3])
        : "r"(a[0]), "r"(a[1]), "r"(a[2]), "r"(a[3]),
          "r"(b[0]), "r"(b[1]));
}

__device__ __forceinline__ void ldsm4(unsigned* r, unsigned addr) {
    asm volatile("ldmatrix.sync.aligned.m8n8.x4.shared.b16 {%0,%1,%2,%3}, [%4];"
        : "=r"(r[0]), "=r"(r[1]), "=r"(r[2]), "=r"(r[3]) : "r"(addr));
}

__device__ __forceinline__ unsigned cvta_s(const void* p) {
    return (unsigned)__cvta_generic_to_shared(p);
}

__device__ __forceinline__ float warp_sum(float v) {
    #pragma unroll
    for (int o = 16; o > 0; o >>= 1) v += __shfl_xor_sync(0xffffffffu, v, o);
    return v;
}
__device__ __forceinline__ float block_sum(float v, float* sm) {
    v = warp_sum(v);
    int w = threadIdx.x >> 5, l = threadIdx.x & 31;
    if (l == 0) sm[w] = v;
    __syncthreads();
    float r = (l < 8) ? sm[l] : 0.0f;
    r = warp_sum(r);
    __syncthreads();
    return r;
}

// ---------------- weight split + transpose (once per launch) --------------
__global__ __launch_bounds__(256) void wsplitT_kernel(
    const float* __restrict__ W, unsigned* __restrict__ hi,
    unsigned* __restrict__ lo, int K2, int N,
    size_t wstride, size_t ostride)
{
    __shared__ float s0[32][33], s1[32][33];
    const float* Wl = W + (size_t)blockIdx.z * wstride;
    int kp0 = blockIdx.x * 32;
    int n0  = blockIdx.y * 32;
    int tx = threadIdx.x & 31, ty = threadIdx.x >> 5;
    #pragma unroll
    for (int i = ty; i < 32; i += 8) {
        int kp = kp0 + i;
        int n = n0 + tx;
        float v0 = 0.0f, v1 = 0.0f;
        if (n < N) {
            v0 = Wl[(size_t)(2 * kp) * N + n];
            v1 = Wl[(size_t)(2 * kp + 1) * N + n];
        }
        s0[i][tx] = v0; s1[i][tx] = v1;
    }
    __syncthreads();
    unsigned* hil = hi + (size_t)blockIdx.z * ostride;
    unsigned* lol = lo + (size_t)blockIdx.z * ostride;
    #pragma unroll
    for (int i = ty; i < 32; i += 8) {
        int n = n0 + i;
        if (n < N) {
            unsigned h, l;
            split2(s0[tx][i], s1[tx][i], h, l);
            hil[(size_t)n * K2 + kp0 + tx] = h;
            lol[(size_t)n * K2 + kp0 + tx] = l;
        }
    }
}

// ---------------- embedding ----------------
__global__ __launch_bounds__(256) void embed_kernel(
    const int* __restrict__ x, const float* __restrict__ wte,
    const float* __restrict__ wpe, float* __restrict__ h)
{
    int i = blockIdx.x * 256 + threadIdx.x;
    if (i < TOK * EMB) {
        int t = i / EMB;
        int e = i - t * EMB;
        int s = t & (SEQ - 1);
        h[i] = wte[(size_t)x[t] * EMB + e] + wpe[(size_t)s * EMB + e];
    }
}

// ---------------- fused layernorm + split (row = 768) ---------------------
// Writes packed bf16x2 hi/lo words directly (no fp32 intermediate).
__global__ __launch_bounds__(256) void ln_split_kernel(
    const float* __restrict__ x, const float* __restrict__ g,
    const float* __restrict__ b, unsigned* __restrict__ hi,
    unsigned* __restrict__ lo)
{
    __shared__ float red[8];
    int row = blockIdx.x;
    int tid = threadIdx.x;
    const float2* xr = (const float2*)(x + (size_t)row * EMB);  // 384 words
    float2 a0 = xr[tid];
    float2 a1 = make_float2(0.0f, 0.0f);
    if (tid < 128) a1 = xr[256 + tid];
    float s  = a0.x + a0.y + a1.x + a1.y;
    float s2 = a0.x * a0.x + a0.y * a0.y + a1.x * a1.x + a1.y * a1.y;
    s  = block_sum(s,  red);
    __syncthreads();
    s2 = block_sum(s2, red);
    float mean = s * (1.0f / EMB);
    float var  = s2 * (1.0f / EMB) - mean * mean;
    float inv  = rsqrtf(var + 1e-5f);
    const float2* g2 = (const float2*)g;
    const float2* b2 = (const float2*)b;
    size_t base = (size_t)row * KW;
    {
        float2 gg = g2[tid], bb = b2[tid];
        unsigned hw, lw;
        split2((a0.x - mean) * inv * gg.x + bb.x,
               (a0.y - mean) * inv * gg.y + bb.y, hw, lw);
        hi[base + tid] = hw; lo[base + tid] = lw;
    }
    if (tid < 128) {
        float2 gg = g2[256 + tid], bb = b2[256 + tid];
        unsigned hw, lw;
        split2((a1.x - mean) * inv * gg.x + bb.x,
               (a1.y - mean) * inv * gg.y + bb.y, hw, lw);
        hi[base + 256 + tid] = hw; lo[base + 256 + tid] = lw;
    }
}

// ---------------- split-bf16 tensor-core GEMM (ldmatrix, reg prefetch) ----
// C[M,N] = A[M,K] @ B^T. EPI: 0=write fp32, 2=residual-accum fp32,
// 3=gelu + split-out to Oh/Ol (packed words along N).
template <int EPI>
__global__ __launch_bounds__(256) void mma_gemm_kernel(
    const unsigned* __restrict__ A_h, const unsigned* __restrict__ A_l,
    const unsigned* __restrict__ B_h, const unsigned* __restrict__ B_l,
    const float* __restrict__ bias, float* __restrict__ C,
    unsigned* __restrict__ Oh, unsigned* __restrict__ Ol,
    int M, int N, int K2)
{
    __shared__ unsigned Ah[128][20], Al[128][20];
    __shared__ unsigned Bh[128][20], Bl[128][20];

    int tid  = threadIdx.x;
    int lane = tid & 31;
    int wid  = tid >> 5;
    int g    = lane >> 2;      // 0..7
    int t4   = lane & 3;       // 0..3
    int wm   = (wid & 3) * 32;
    int wn   = (wid >> 2) * 64;

    int bm = blockIdx.y * 128;
    int bn = blockIdx.x * 128;

    float acc[2][8][4];
    #pragma unroll
    for (int mi = 0; mi < 2; mi++)
        #pragma unroll
        for (int nj = 0; nj < 8; nj++)
            #pragma unroll
            for (int e = 0; e < 4; e++) acc[mi][nj][e] = 0.0f;

    unsigned aBH = cvta_s(&Ah[wm + (lane & 15)][(lane >> 4) * 4]);
    unsigned aBL = cvta_s(&Al[wm + (lane & 15)][(lane >> 4) * 4]);
    unsigned bBH = cvta_s(&Bh[wn + ((lane >> 4) * 8) + (lane & 7)][((lane >> 3) & 1) * 4]);
    unsigned bBL = cvta_s(&Bl[wn + ((lane >> 4) * 8) + (lane & 7)][((lane >> 3) & 1) * 4]);

    int r[2], c[2];
    bool okB[2];
    #pragma unroll
    for (int i = 0; i < 2; i++) {
        int idx = tid + 256 * i;
        r[i] = idx >> 2;
        c[i] = (idx & 3) * 4;
        okB[i] = (bn + r[i]) < N;
    }

    uint4 sah[2], sal[2], sbh[2], sbl[2];
    const uint4 zero4 = make_uint4(0, 0, 0, 0);

    #pragma unroll
    for (int i = 0; i < 2; i++) {
        size_t ao = (size_t)(bm + r[i]) * K2 + c[i];
        sah[i] = *(const uint4*)(A_h + ao);
        sal[i] = *(const uint4*)(A_l + ao);
        size_t bo = (size_t)(bn + r[i]) * K2 + c[i];
        sbh[i] = okB[i] ? *(const uint4*)(B_h + bo) : zero4;
        sbl[i] = okB[i] ? *(const uint4*)(B_l + bo) : zero4;
    }

    for (int k0 = 0; k0 < K2; k0 += 16) {
        #pragma unroll
        for (int i = 0; i < 2; i++) {
            *(uint4*)&Ah[r[i]][c[i]] = sah[i];
            *(uint4*)&Al[r[i]][c[i]] = sal[i];
            *(uint4*)&Bh[r[i]][c[i]] = sbh[i];
            *(uint4*)&Bl[r[i]][c[i]] = sbl[i];
        }
        __syncthreads();

        int k1 = k0 + 16;
        if (k1 < K2) {
            #pragma unroll
            for (int i = 0; i < 2; i++) {
                size_t ao = (size_t)(bm + r[i]) * K2 + k1 + c[i];
                sah[i] = *(const uint4*)(A_h + ao);
                sal[i] = *(const uint4*)(A_l + ao);
                size_t bo = (size_t)(bn + r[i]) * K2 + k1 + c[i];
                sbh[i] = okB[i] ? *(const uint4*)(B_h + bo) : zero4;
                sbl[i] = okB[i] ? *(const uint4*)(B_l + bo) : zero4;
            }
        }

        #pragma unroll
        for (int ch = 0; ch < 2; ch++) {
            int kc = ch * 8;
            unsigned ah2[2][4], al2[2][4];
            #pragma unroll
            for (int mi = 0; mi < 2; mi++) {
                unsigned off = (unsigned)(mi * 16 * 20 + kc) * 4u;
                ldsm4(ah2[mi], aBH + off);
                ldsm4(al2[mi], aBL + off);
            }
            #pragma unroll
            for (int njp = 0; njp < 4; njp++) {
                unsigned off = (unsigned)(njp * 16 * 20 + kc) * 4u;
                unsigned bh4[4], bl4[4];
                ldsm4(bh4, bBH + off);
                ldsm4(bl4, bBL + off);
                #pragma unroll
                for (int half = 0; half < 2; half++) {
                    int nj = njp * 2 + half;
                    #pragma unroll
                    for (int mi = 0; mi < 2; mi++) {
                        mma_bf16(acc[mi][nj], ah2[mi], bh4 + 2 * half);
                        mma_bf16(acc[mi][nj], ah2[mi], bl4 + 2 * half);
                        mma_bf16(acc[mi][nj], al2[mi], bh4 + 2 * half);
                    }
                }
            }
        }
        __syncthreads();
    }

    // ---- epilogue ----
    #pragma unroll
    for (int mi = 0; mi < 2; mi++) {
        int rr = bm + wm + mi * 16 + g;
        #pragma unroll
        for (int nj = 0; nj < 8; nj++) {
            int cb = bn + wn + nj * 8 + 2 * t4;
            if (EPI == 3) {
                // gelu + split-out (pairs cb, cb+1 -> word cb/2)
                #pragma unroll
                for (int half = 0; half < 2; half++) {
                    int row = rr + half * 8;
                    float v0 = gelu_f(acc[mi][nj][2 * half]     + bias[cb]);
                    float v1 = gelu_f(acc[mi][nj][2 * half + 1] + bias[cb + 1]);
                    unsigned hw, lw;
                    split2(v0, v1, hw, lw);
                    size_t wi = (size_t)row * (N / 2) + (cb >> 1);
                    Oh[wi] = hw; Ol[wi] = lw;
                }
            } else {
                #pragma unroll
                for (int e = 0; e < 4; e++) {
                    int row = rr + (e >> 1) * 8;
                    int col = cb + (e & 1);
                    if (col < N) {
                        float v = acc[mi][nj][e];
                        if (bias) v += bias[col];
                        size_t idx = (size_t)row * N + col;
                        if (EPI == 2) v += C[idx];
                        C[idx] = v;
                    }
                }
            }
        }
    }
}

// ---------------- fused flash attention (split-word output) ---------------
__global__ __launch_bounds__(256) void flash_kernel(
    const float* __restrict__ qkv,
    unsigned* __restrict__ yh, unsigned* __restrict__ yl)
{
    __shared__ unsigned fsm[9216];
    int qt = blockIdx.x, bh = blockIdx.y;
    int b = bh / HEADS, h = bh - b * HEADS;
    int tid = threadIdx.x, lane = tid & 31, wid = tid >> 5;
    int g = lane >> 2, t4 = lane & 3;

    unsigned (*Qh)[36] = (unsigned(*)[36])(fsm);
    unsigned (*Ql)[36] = (unsigned(*)[36])(fsm + 4608);
    unsigned (*Kh)[36] = (unsigned(*)[36])(fsm);
    unsigned (*Kl)[36] = (unsigned(*)[36])(fsm + 2304);
    unsigned (*Vh)[72] = (unsigned(*)[72])(fsm + 4608);
    unsigned (*Vl)[72] = (unsigned(*)[72])(fsm + 6912);

    const float* qb = qkv + (size_t)(b * SEQ + qt * 128) * E3 + h * DHEAD;

    #pragma unroll
    for (int i = 0; i < 8; i++) {
        int idx = tid + 256 * i;
        int rr = idx >> 4;
        int d = (idx & 15) * 4;
        int w = d >> 1;
        float4 qv = *(const float4*)(qb + (size_t)rr * E3 + d);
        unsigned h0, l0, h1, l1;
        split2(qv.x, qv.y, h0, l0); split2(qv.z, qv.w, h1, l1);
        Qh[rr][w] = h0; Qh[rr][w + 1] = h1;
        Ql[rr][w] = l0; Ql[rr][w + 1] = l1;
    }
    __syncthreads();

    int m = wid * 16 + g;
    unsigned qh[4][4], ql[4][4];
    #pragma unroll
    for (int ch = 0; ch < 4; ch++) {
        int kc = ch * 8;
        qh[ch][0] = Qh[m][kc + t4];     qh[ch][1] = Qh[m + 8][kc + t4];
        qh[ch][2] = Qh[m][kc + t4 + 4]; qh[ch][3] = Qh[m + 8][kc + t4 + 4];
        ql[ch][0] = Ql[m][kc + t4];     ql[ch][1] = Ql[m + 8][kc + t4];
        ql[ch][2] = Ql[m][kc + t4 + 4]; ql[ch][3] = Ql[m + 8][kc + t4 + 4];
    }
    __syncthreads();

    float mrow[2] = { -3.0e38f, -3.0e38f };
    float lrow[2] = { 0.0f, 0.0f };
    float o[8][4];
    #pragma unroll
    for (int nj = 0; nj < 8; nj++)
        #pragma unroll
        for (int e = 0; e < 4; e++) o[nj][e] = 0.0f;

    const float* kbase = qkv + (size_t)(b * SEQ) * E3 + EMB + h * DHEAD;
    const float* vbase = qkv + (size_t)(b * SEQ) * E3 + 2 * EMB + h * DHEAD;
    int row0 = qt * 128 + m;

    int ktmax = 2 * qt + 1;
    for (int kt = 0; kt <= ktmax; kt++) {
        #pragma unroll
        for (int i = 0; i < 4; i++) {
            int idx = tid + 256 * i;
            int rr = idx >> 4;
            int d = (idx & 15) * 4;
            int w = d >> 1;
            float4 kv = *(const float4*)(kbase + (size_t)(kt * 64 + rr) * E3 + d);
            unsigned h0, l0, h1, l1;
            split2(kv.x, kv.y, h0, l0); split2(kv.z, kv.w, h1, l1);
            Kh[rr][w] = h0; Kh[rr][w + 1] = h1;
            Kl[rr][w] = l0; Kl[rr][w + 1] = l1;
        }
        #pragma unroll
        for (int i = 0; i < 2; i++) {
            int idx = tid + 256 * i;
            int kp = idx >> 4;
            int cc = (idx & 15) * 4;
            const float* v0p = vbase + (size_t)(kt * 64 + 2 * kp) * E3 + cc;
            float4 v0 = *(const float4*)(v0p);
            float4 v1 = *(const float4*)(v0p + E3);
            unsigned hw, lw;
            split2(v0.x, v1.x, hw, lw); Vh[kp][cc]     = hw; Vl[kp][cc]     = lw;
            split2(v0.y, v1.y, hw, lw); Vh[kp][cc + 1] = hw; Vl[kp][cc + 1] = lw;
            split2(v0.z, v1.z, hw, lw); Vh[kp][cc + 2] = hw; Vl[kp][cc + 2] = lw;
            split2(v0.w, v1.w, hw, lw); Vh[kp][cc + 3] = hw; Vl[kp][cc + 3] = lw;
        }
        __syncthreads();

        float s[8][4];
        #pragma unroll
        for (int nj = 0; nj < 8; nj++)
            #pragma unroll
            for (int e = 0; e < 4; e++) s[nj][e] = 0.0f;
        #pragma unroll
        for (int ch = 0; ch < 4; ch++) {
            int kc = ch * 8;
            #pragma unroll
            for (int nj = 0; nj < 8; nj++) {
                int n = nj * 8 + g;
                unsigned bhf[2] = { Kh[n][kc + t4], Kh[n][kc + t4 + 4] };
                unsigned blf[2] = { Kl[n][kc + t4], Kl[n][kc + t4 + 4] };
                mma_bf16(s[nj], qh[ch], bhf);
                mma_bf16(s[nj], qh[ch], blf);
                mma_bf16(s[nj], ql[ch], bhf);
            }
        }

        #pragma unroll
        for (int nj = 0; nj < 8; nj++)
            #pragma unroll
            for (int e = 0; e < 4; e++) {
                int col = kt * 64 + nj * 8 + 2 * t4 + (e & 1);
                int row = row0 + (e >> 1) * 8;
                s[nj][e] = (col <= row) ? s[nj][e] * 0.125f : -3.0e38f;
            }

        #pragma unroll
        for (int half = 0; half < 2; half++) {
            float mx = -3.0e38f;
            #pragma unroll
            for (int nj = 0; nj < 8; nj++)
                mx = fmaxf(mx, fmaxf(s[nj][2 * half], s[nj][2 * half + 1]));
            mx = fmaxf(mx, __shfl_xor_sync(0xffffffffu, mx, 1));
            mx = fmaxf(mx, __shfl_xor_sync(0xffffffffu, mx, 2));
            float mn = fmaxf(mrow[half], mx);
            float sc = __expf(mrow[half] - mn);
            mrow[half] = mn;
            float sum = 0.0f;
            #pragma unroll
            for (int nj = 0; nj < 8; nj++) {
                float p0 = __expf(s[nj][2 * half]     - mn);
                float p1 = __expf(s[nj][2 * half + 1] - mn);
                s[nj][2 * half] = p0; s[nj][2 * half + 1] = p1;
                sum += p0 + p1;
            }
            sum += __shfl_xor_sync(0xffffffffu, sum, 1);
            sum += __shfl_xor_sync(0xffffffffu, sum, 2);
            lrow[half] = lrow[half] * sc + sum;
            #pragma unroll
            for (int nj = 0; nj < 8; nj++) {
                o[nj][2 * half]     *= sc;
                o[nj][2 * half + 1] *= sc;
            }
        }

        #pragma unroll
        for (int ch = 0; ch < 4; ch++) {
            unsigned ph[4], pl[4];
            split2(s[2 * ch][0],     s[2 * ch][1],     ph[0], pl[0]);
            split2(s[2 * ch][2],     s[2 * ch][3],     ph[1], pl[1]);
            split2(s[2 * ch + 1][0], s[2 * ch + 1][1], ph[2], pl[2]);
            split2(s[2 * ch + 1][2], s[2 * ch + 1][3], ph[3], pl[3]);
            int kc = ch * 8;
            #pragma unroll
            for (int njd = 0; njd < 8; njd++) {
                int n = njd * 8 + g;
                unsigned bh2[2] = { Vh[kc + t4][n], Vh[kc + t4 + 4][n] };
                unsigned bl2[2] = { Vl[kc + t4][n], Vl[kc + t4 + 4][n] };
                mma_bf16(o[njd], ph, bh2);
                mma_bf16(o[njd], ph, bl2);
                mma_bf16(o[njd], pl, bh2);
            }
        }
        __syncthreads();
    }

    // ---- epilogue: normalize and store SPLIT words directly ----
    float inv0 = 1.0f / lrow[0];
    float inv1 = 1.0f / lrow[1];
    #pragma unroll
    for (int njd = 0; njd < 8; njd++) {
        int word = h * 32 + njd * 4 + t4;
        #pragma unroll
        for (int half = 0; half < 2; half++) {
            int row = row0 + half * 8;
            float inv = half ? inv1 : inv0;
            unsigned hw, lw;
            split2(o[njd][2 * half] * inv, o[njd][2 * half + 1] * inv, hw, lw);
            size_t wi = (size_t)(b * SEQ + row) * KW + word;
            yh[wi] = hw; yl[wi] = lw;
        }
    }
}

// ---------------- launch ----------------
static inline int cdiv(size_t a, int b) { return (int)((a + b - 1) / b); }

extern "C" void kernel_launch(void* const* d_in, const int* in_sizes, int n_in,
                              void* d_out, int out_size)
{
    const int*   x    = (const int*)  d_in[0];
    const float* wte  = (const float*)d_in[1];
    const float* wpe  = (const float*)d_in[2];
    const float* ln1g = (const float*)d_in[3];
    const float* ln1b = (const float*)d_in[4];
    const float* attw = (const float*)d_in[5];
    const float* attb = (const float*)d_in[6];
    const float* apw  = (const float*)d_in[7];
    const float* apb  = (const float*)d_in[8];
    const float* ln2g = (const float*)d_in[9];
    const float* ln2b = (const float*)d_in[10];
    const float* fcw  = (const float*)d_in[11];
    const float* fcb  = (const float*)d_in[12];
    const float* fpw  = (const float*)d_in[13];
    const float* fpb  = (const float*)d_in[14];
    const float* lnfg = (const float*)d_in[15];
    const float* lnfb = (const float*)d_in[16];
    const float* lmw  = (const float*)d_in[17];
    float* out = (float*)d_out;

    float *h, *qkv;
    unsigned *wqh, *wql, *waph, *wapl, *wfch, *wfcl, *wfph, *wfpl, *wlmh, *wlml;
    unsigned *ah, *al, *fh, *fl;
    cudaGetSymbolAddress((void**)&h,    g_h);
    cudaGetSymbolAddress((void**)&qkv,  g_qkv);
    cudaGetSymbolAddress((void**)&wqh,  g_wqkv_h);
    cudaGetSymbolAddress((void**)&wql,  g_wqkv_l);
    cudaGetSymbolAddress((void**)&waph, g_wap_h);
    cudaGetSymbolAddress((void**)&wapl, g_wap_l);
    cudaGetSymbolAddress((void**)&wfch, g_wfc_h);
    cudaGetSymbolAddress((void**)&wfcl, g_wfc_l);
    cudaGetSymbolAddress((void**)&wfph, g_wfp_h);
    cudaGetSymbolAddress((void**)&wfpl, g_wfp_l);
    cudaGetSymbolAddress((void**)&wlmh, g_wlm_h);
    cudaGetSymbolAddress((void**)&wlml, g_wlm_l);
    cudaGetSymbolAddress((void**)&ah,   g_ah);
    cudaGetSymbolAddress((void**)&al,   g_al);
    cudaGetSymbolAddress((void**)&fh,   g_fh);
    cudaGetSymbolAddress((void**)&fl,   g_fl);

    embed_kernel<<<(TOK * EMB + 255) / 256, 256>>>(x, wte, wpe, h);

    // ---- pre-split + transpose all weights (once per launch) ----
    wsplitT_kernel<<<dim3(KW / 32, E3 / 32, LAYERS), 256>>>(
        attw, wqh, wql, KW, E3, (size_t)EMB * E3, (size_t)E3 * KW);
    wsplitT_kernel<<<dim3(KW / 32, EMB / 32, LAYERS), 256>>>(
        apw, waph, wapl, KW, EMB, (size_t)EMB * EMB, (size_t)EMB * KW);
    wsplitT_kernel<<<dim3(KW / 32, E4 / 32, LAYERS), 256>>>(
        fcw, wfch, wfcl, KW, E4, (size_t)EMB * E4, (size_t)E4 * KW);
    wsplitT_kernel<<<dim3(KW4 / 32, EMB / 32, LAYERS), 256>>>(
        fpw, wfph, wfpl, KW4, EMB, (size_t)E4 * EMB, (size_t)EMB * KW4);
    wsplitT_kernel<<<dim3(KW / 32, cdiv(VOCAB, 32), 1), 256>>>(
        lmw, wlmh, wlml, KW, VOCAB, 0, 0);

    for (int l = 0; l < LAYERS; l++) {
        ln_split_kernel<<<TOK, 256>>>(h, ln1g + l * EMB, ln1b + l * EMB, ah, al);
        mma_gemm_kernel<0><<<dim3(E3 / 128, TOK / 128), 256>>>(
            ah, al, wqh + (size_t)l * E3 * KW, wql + (size_t)l * E3 * KW,
            attb + (size_t)l * E3, qkv, nullptr, nullptr, TOK, E3, KW);

        flash_kernel<<<dim3(SEQ / 128, BATCH * HEADS), 256>>>(qkv, ah, al);

        mma_gemm_kernel<2><<<dim3(EMB / 128, TOK / 128), 256>>>(
            ah, al, waph + (size_t)l * EMB * KW, wapl + (size_t)l * EMB * KW,
            apb + (size_t)l * EMB, h, nullptr, nullptr, TOK, EMB, KW);

        ln_split_kernel<<<TOK, 256>>>(h, ln2g + l * EMB, ln2b + l * EMB, ah, al);
        mma_gemm_kernel<3><<<dim3(E4 / 128, TOK / 128), 256>>>(
            ah, al, wfch + (size_t)l * E4 * KW, wfcl + (size_t)l * E4 * KW,
            fcb + (size_t)l * E4, nullptr, fh, fl, TOK, E4, KW);

        mma_gemm_kernel<2><<<dim3(EMB / 128, TOK / 128), 256>>>(
            fh, fl, wfph + (size_t)l * EMB * KW4, wfpl + (size_t)l * EMB * KW4,
            fpb + (size_t)l * EMB, h, nullptr, nullptr, TOK, EMB, KW4);
    }

    ln_split_kernel<<<TOK, 256>>>(h, lnfg, lnfb, ah, al);
    mma_gemm_kernel<0><<<dim3(cdiv(VOCAB, 128), TOK / 128), 256>>>(
        ah, al, wlmh, wlml, nullptr, out, nullptr, nullptr, TOK, VOCAB, KW);
}